// round 1
// baseline (speedup 1.0000x reference)
#include <cuda_runtime.h>
#include <cfloat>
#include <climits>
#include <cstdint>

// Problem constants
#define NQ    2048      // 4*512 queries
#define NK    65536     // keys/values rows
#define DIM   256
#define TOPK  32

// Tiling
#define TM      64               // queries per CTA
#define SLICE   2048             // keys per CTA (key-split)
#define CHUNK   128              // keys per staging chunk
#define NSLICES (NK / SLICE)     // 32
#define NQT     (NQ / TM)        // 32
#define NCHUNK  (SLICE / CHUNK)  // 16
#define NKS     (DIM / 16)       // 16 k-slices of 16

// Shared memory layout (floats)
#define BS_ROW 132
#define SS_ROW 134
#define AS_F   (DIM * TM)            // 16384
#define BS_F   (2 * 16 * BS_ROW)     // 4224
#define SS_F   (TM * SS_ROW)         // 8576
#define TV_F   (TM * TOPK)           // 2048
#define SMEM_FLOATS (AS_F + BS_F + SS_F + TV_F + TV_F)
#define SMEM_BYTES  (SMEM_FLOATS * 4)   // 133120 B

// Partial top-k scratch (device globals: sanctioned scratch, no allocs)
__device__ float g_pv[NQ * NSLICES * TOPK];   // 8 MB
__device__ int   g_pi[NQ * NSLICES * TOPK];   // 8 MB

// ---- Blackwell packed f32x2 helpers --------------------------------------
__device__ __forceinline__ unsigned long long ffma2(unsigned long long a,
                                                    unsigned long long b,
                                                    unsigned long long c) {
    unsigned long long d;
    asm("fma.rn.f32x2 %0, %1, %2, %3;" : "=l"(d) : "l"(a), "l"(b), "l"(c));
    return d;
}
__device__ __forceinline__ unsigned long long pack2(float x) {
    unsigned long long d;
    asm("mov.b64 %0, {%1, %1};" : "=l"(d) : "f"(x));
    return d;
}

// ---- Kernel 1: fused GEMM + per-slice streaming top-32 -------------------
// grid: (NSLICES, NQT), 256 threads.
// Thread (r = tid>>4, c = tid&15) computes queries r*4..r*4+3 against keys
// {c*4..c*4+3} U {64+c*4..64+c*4+3} of each 128-key chunk, K fully reduced.
__global__ __launch_bounds__(256)
void score_topk_kernel(const float* __restrict__ query,
                       const float* __restrict__ keys) {
    extern __shared__ float smem[];
    float* As = smem;                 // [DIM][TM]   (d-major, transposed)
    float* Bs = As + AS_F;            // [2][16][BS_ROW]
    float* Ss = Bs + BS_F;            // [TM][SS_ROW]
    float* Tv = Ss + SS_F;            // [TM][TOPK]
    int*   Ti = (int*)(Tv + TV_F);    // [TM][TOPK]

    const int tid = threadIdx.x;
    const int r = tid >> 4;           // 0..15
    const int c = tid & 15;           // 0..15

    // --- load the 64x256 query tile once, transposed to As[d][q] ---
    const float* Aq = query + (size_t)blockIdx.y * TM * DIM;
    for (int i = tid; i < TM * (DIM / 4); i += 256) {
        int q  = i >> 6;              // 0..63
        int f4 = i & 63;              // float4 index along d
        float4 v = *(const float4*)(Aq + q * DIM + f4 * 4);
        int d0 = f4 * 4;
        As[(d0 + 0) * TM + q] = v.x;
        As[(d0 + 1) * TM + q] = v.y;
        As[(d0 + 2) * TM + q] = v.z;
        As[(d0 + 3) * TM + q] = v.w;
    }
    // --- init top-k state ---
    for (int i = tid; i < TM * TOPK; i += 256) { Tv[i] = -FLT_MAX; Ti[i] = 0; }
    __syncthreads();

    // per-scanning-thread running min (thread tid<64 always owns query tid)
    float minv = -FLT_MAX;
    int   minslot = 0;

    const float* Bbase = keys + (size_t)blockIdx.x * SLICE * DIM;
    const int bkey = tid >> 1;            // 0..127
    const int bd   = (tid & 1) * 8;       // 0 or 8 within 16-wide k-slice

    for (int ch = 0; ch < NCHUNK; ++ch) {
        const float* Bc = Bbase + (size_t)ch * CHUNK * DIM;

        // load k-slice 0 of this chunk into Bs[0]
        {
            float4 u0 = *(const float4*)(Bc + bkey * DIM + bd);
            float4 u1 = *(const float4*)(Bc + bkey * DIM + bd + 4);
            float* Bw = Bs;
            Bw[(bd + 0) * BS_ROW + bkey] = u0.x;
            Bw[(bd + 1) * BS_ROW + bkey] = u0.y;
            Bw[(bd + 2) * BS_ROW + bkey] = u0.z;
            Bw[(bd + 3) * BS_ROW + bkey] = u0.w;
            Bw[(bd + 4) * BS_ROW + bkey] = u1.x;
            Bw[(bd + 5) * BS_ROW + bkey] = u1.y;
            Bw[(bd + 6) * BS_ROW + bkey] = u1.z;
            Bw[(bd + 7) * BS_ROW + bkey] = u1.w;
        }
        __syncthreads();

        unsigned long long acc[4][4];
        #pragma unroll
        for (int i = 0; i < 4; ++i)
            #pragma unroll
            for (int j = 0; j < 4; ++j) acc[i][j] = 0ULL;

        int buf = 0;
        #pragma unroll 1
        for (int ks = 0; ks < NKS; ++ks) {
            float4 n0, n1;
            if (ks < NKS - 1) {
                n0 = *(const float4*)(Bc + bkey * DIM + (ks + 1) * 16 + bd);
                n1 = *(const float4*)(Bc + bkey * DIM + (ks + 1) * 16 + bd + 4);
            }
            const float* Bp = Bs + buf * (16 * BS_ROW);
            const float* Ap = As + ks * 16 * TM;
            #pragma unroll
            for (int kk = 0; kk < 16; ++kk) {
                float4 av = *(const float4*)(Ap + kk * TM + (r << 2));
                ulonglong2 b01 = *(const ulonglong2*)(Bp + kk * BS_ROW + (c << 2));
                ulonglong2 b23 = *(const ulonglong2*)(Bp + kk * BS_ROW + 64 + (c << 2));
                unsigned long long a0 = pack2(av.x);
                unsigned long long a1 = pack2(av.y);
                unsigned long long a2 = pack2(av.z);
                unsigned long long a3 = pack2(av.w);
                acc[0][0] = ffma2(a0, b01.x, acc[0][0]);
                acc[0][1] = ffma2(a0, b01.y, acc[0][1]);
                acc[0][2] = ffma2(a0, b23.x, acc[0][2]);
                acc[0][3] = ffma2(a0, b23.y, acc[0][3]);
                acc[1][0] = ffma2(a1, b01.x, acc[1][0]);
                acc[1][1] = ffma2(a1, b01.y, acc[1][1]);
                acc[1][2] = ffma2(a1, b23.x, acc[1][2]);
                acc[1][3] = ffma2(a1, b23.y, acc[1][3]);
                acc[2][0] = ffma2(a2, b01.x, acc[2][0]);
                acc[2][1] = ffma2(a2, b01.y, acc[2][1]);
                acc[2][2] = ffma2(a2, b23.x, acc[2][2]);
                acc[2][3] = ffma2(a2, b23.y, acc[2][3]);
                acc[3][0] = ffma2(a3, b01.x, acc[3][0]);
                acc[3][1] = ffma2(a3, b01.y, acc[3][1]);
                acc[3][2] = ffma2(a3, b23.x, acc[3][2]);
                acc[3][3] = ffma2(a3, b23.y, acc[3][3]);
            }
            if (ks < NKS - 1) {
                float* Bw = Bs + (buf ^ 1) * (16 * BS_ROW);
                Bw[(bd + 0) * BS_ROW + bkey] = n0.x;
                Bw[(bd + 1) * BS_ROW + bkey] = n0.y;
                Bw[(bd + 2) * BS_ROW + bkey] = n0.z;
                Bw[(bd + 3) * BS_ROW + bkey] = n0.w;
                Bw[(bd + 4) * BS_ROW + bkey] = n1.x;
                Bw[(bd + 5) * BS_ROW + bkey] = n1.y;
                Bw[(bd + 6) * BS_ROW + bkey] = n1.z;
                Bw[(bd + 7) * BS_ROW + bkey] = n1.w;
            }
            __syncthreads();
            buf ^= 1;
        }

        // --- stage chunk scores to smem (packed 8B stores) ---
        #pragma unroll
        for (int i = 0; i < 4; ++i) {
            int q = (r << 2) + i;
            float* row = Ss + q * SS_ROW;
            *(unsigned long long*)(row + (c << 2))       = acc[i][0];
            *(unsigned long long*)(row + (c << 2) + 2)   = acc[i][1];
            *(unsigned long long*)(row + 64 + (c << 2))  = acc[i][2];
            *(unsigned long long*)(row + 64 + (c << 2) + 2) = acc[i][3];
        }
        __syncthreads();

        // --- streaming top-32 update: thread q scans its 128 chunk scores ---
        if (tid < TM) {
            const int q = tid;
            const int gbase = blockIdx.x * SLICE + ch * CHUNK;
            const float* srow = Ss + q * SS_ROW;
            float* Trow = Tv + q * TOPK;
            int*   Irow = Ti + q * TOPK;
            for (int k = 0; k < CHUNK; ++k) {
                float s = srow[k];
                if (s > minv) {
                    Trow[minslot] = s;
                    Irow[minslot] = gbase + k;
                    // rescan for new min
                    float m = Trow[0]; int ms = 0;
                    for (int j = 1; j < TOPK; ++j) {
                        float v = Trow[j];
                        if (v < m) { m = v; ms = j; }
                    }
                    minv = m; minslot = ms;
                }
            }
        }
        __syncthreads();
    }

    // --- write per-slice partial top-32 to global ---
    const int qt = blockIdx.y * TM;
    for (int i = tid; i < TM * TOPK; i += 256) {
        int q = i >> 5, j = i & 31;
        size_t off = (((size_t)(qt + q)) * NSLICES + blockIdx.x) * TOPK + j;
        g_pv[off] = Tv[q * TOPK + j];
        g_pi[off] = Ti[q * TOPK + j];
    }
}

// ---- Kernel 2: merge partials, softmax, gather values --------------------
// grid: NQ CTAs, 256 threads (one thread per output dim).
__global__ __launch_bounds__(256)
void topk_merge_kernel(const float* __restrict__ vals,
                       float* __restrict__ out) {
    __shared__ float cv[NSLICES * TOPK];   // 1024 candidates
    __shared__ int   ci[NSLICES * TOPK];
    __shared__ float redv[256];
    __shared__ int   redi[256];
    __shared__ int   redp[256];
    __shared__ float sscore[TOPK];
    __shared__ int   sidx[TOPK];
    __shared__ float wts[TOPK];

    const int q = blockIdx.x;
    const int tid = threadIdx.x;

    for (int i = tid; i < NSLICES * TOPK; i += 256) {
        cv[i] = g_pv[(size_t)q * (NSLICES * TOPK) + i];
        ci[i] = g_pi[(size_t)q * (NSLICES * TOPK) + i];
    }
    __syncthreads();

    // exact top-32 of the 1024 candidates (tie-break: lower key index)
    for (int it = 0; it < TOPK; ++it) {
        float bv = -FLT_MAX; int bi = INT_MAX; int bp = 0;
        for (int i = tid; i < NSLICES * TOPK; i += 256) {
            float v = cv[i]; int ii = ci[i];
            if (v > bv || (v == bv && ii < bi)) { bv = v; bi = ii; bp = i; }
        }
        redv[tid] = bv; redi[tid] = bi; redp[tid] = bp;
        __syncthreads();
        for (int s = 128; s > 0; s >>= 1) {
            if (tid < s) {
                float ov = redv[tid + s]; int oi = redi[tid + s];
                if (ov > redv[tid] || (ov == redv[tid] && oi < redi[tid])) {
                    redv[tid] = ov; redi[tid] = oi; redp[tid] = redp[tid + s];
                }
            }
            __syncthreads();
        }
        if (tid == 0) {
            int p = redp[0];
            sscore[it] = cv[p];
            sidx[it]   = ci[p];
            cv[p] = -FLT_MAX;
        }
        __syncthreads();
    }

    // softmax over the 32 selected (scaled) scores — warp 0
    if (tid < 32) {
        float s = sscore[tid] * 0.0625f;   // D_MODEL^-0.5
        float m = s;
        #pragma unroll
        for (int o = 16; o > 0; o >>= 1) m = fmaxf(m, __shfl_xor_sync(0xffffffffu, m, o));
        float e = expf(s - m);
        float sum = e;
        #pragma unroll
        for (int o = 16; o > 0; o >>= 1) sum += __shfl_xor_sync(0xffffffffu, sum, o);
        wts[tid] = e / sum;
    }
    __syncthreads();

    // gather + weighted sum: thread = one output dim
    const int d = tid;
    float acc = 0.0f;
    #pragma unroll 8
    for (int j = 0; j < TOPK; ++j) {
        acc += wts[j] * __ldg(vals + (size_t)sidx[j] * DIM + d);
    }
    out[(size_t)q * DIM + d] = acc;
}

// ---- Host launch ---------------------------------------------------------
extern "C" void kernel_launch(void* const* d_in, const int* in_sizes, int n_in,
                              void* d_out, int out_size) {
    const float* query = (const float*)d_in[0];   // [4,512,256]
    const float* keys  = (const float*)d_in[1];   // [65536,256]
    const float* vals  = (const float*)d_in[2];   // [65536,256]
    float* out = (float*)d_out;                   // [4,512,256]

    cudaFuncSetAttribute(score_topk_kernel,
                         cudaFuncAttributeMaxDynamicSharedMemorySize, SMEM_BYTES);

    dim3 grid1(NSLICES, NQT);
    score_topk_kernel<<<grid1, 256, SMEM_BYTES>>>(query, keys);
    topk_merge_kernel<<<NQ, 256>>>(vals, out);
}